// round 15
// baseline (speedup 1.0000x reference)
#include <cuda_runtime.h>
#include <cuda_bf16.h>
#include <cstddef>
#include <cstdint>

// ---------------------------------------------------------------------------
// ConvGraphNet (5-layer GCN) on GB300.
// R15: GEMM kernel has TWO bodies selected at compile time per target:
//   - sm_103a / sm_10xf (feature macros defined): tcgen05 bf16x3 SS MMA,
//     TMEM fp32 accumulation, double-buffered cp.async + mbarrier commits.
//   - plain sm_103 / other passes: the proven mma.sync bf16x3 path (R14).
// The driver picks the best cubin; both are correct.
// ---------------------------------------------------------------------------

#if defined(__CUDA_ARCH__) && (defined(__CUDA_ARCH_FEAT_SM103_ALL) || \
    defined(__CUDA_ARCH_FEAT_SM100_ALL) || \
    (defined(__CUDA_ARCH_SPECIFIC__) && (__CUDA_ARCH_SPECIFIC__ >= 1000)) || \
    (defined(__CUDA_ARCH_FAMILY_SPECIFIC__) && (__CUDA_ARCH_FAMILY_SPECIFIC__ >= 1000)))
#define HAS_TCGEN05 1
#endif

#define NODES_MAX 50000
#define EDGES_MAX 400000
#define MPAD_MAX  50048   // 391 * 128

static __device__ float g_bufA[(size_t)NODES_MAX * 1024];
static __device__ float g_bufB[(size_t)NODES_MAX * 1024];
static __device__ float g_dinv[NODES_MAX];
static __device__ int   g_cnt[NODES_MAX];
static __device__ int   g_rows[NODES_MAX + 1];
static __device__ int   g_pos[NODES_MAX];
static __device__ int   g_partial[256];
static __device__ int   g_csr_src[EDGES_MAX];
static __device__ float g_csr_nrm[EDGES_MAX];
static __device__ __nv_bfloat16 g_wthi[1 << 20];
static __device__ __nv_bfloat16 g_wtlo[1 << 20];
static __device__ __nv_bfloat16 g_ahi[(size_t)MPAD_MAX * 512];
static __device__ __nv_bfloat16 g_alo[(size_t)MPAD_MAX * 512];
static __device__ __nv_bfloat16 g_bhi[(size_t)MPAD_MAX * 1024];
static __device__ __nv_bfloat16 g_blo[(size_t)MPAD_MAX * 1024];

// weight-transpose regions inside g_wthi/g_wtlo
#define WOFF1 0          // W1t: 1024 x 128
#define WOFF2 131072     // W2t: 512 x 1024
#define WOFF3 655360     // W3t: 256 x 512
#define WOFF4 786432     // W4t: 128 x 256 (cols 64..127 zero)

// ---------------------------- common helpers --------------------------------

__device__ __forceinline__ uint32_t smem_u32(const void* p) {
    uint32_t a;
    asm("{ .reg .u64 t; cvta.to.shared.u64 t, %1; cvt.u32.u64 %0, t; }"
        : "=r"(a) : "l"(p));
    return a;
}

__device__ __forceinline__ void cpa16(uint32_t s, const void* g) {
    asm volatile("cp.async.cg.shared.global [%0], [%1], 16;" :: "r"(s), "l"(g));
}

__device__ __forceinline__ void ldsm_x4(uint32_t* r, uint32_t addr) {
    asm volatile("ldmatrix.sync.aligned.m8n8.x4.shared.b16 {%0,%1,%2,%3}, [%4];"
                 : "=r"(r[0]), "=r"(r[1]), "=r"(r[2]), "=r"(r[3]) : "r"(addr));
}

__device__ __forceinline__ void mma_bf16(float* d, const uint32_t* a, const uint32_t* b) {
    asm volatile("mma.sync.aligned.m16n8k16.row.col.f32.bf16.bf16.f32 "
                 "{%0,%1,%2,%3}, {%4,%5,%6,%7}, {%8,%9}, {%0,%1,%2,%3};"
                 : "+f"(d[0]), "+f"(d[1]), "+f"(d[2]), "+f"(d[3])
                 : "r"(a[0]), "r"(a[1]), "r"(a[2]), "r"(a[3]), "r"(b[0]), "r"(b[1]));
}

__device__ __forceinline__ void split2(float x, float y, uint32_t& h, uint32_t& l) {
    __nv_bfloat162 hb = __floats2bfloat162_rn(x, y);
    float2 hf = __bfloat1622float2(hb);
    __nv_bfloat162 lb = __floats2bfloat162_rn(x - hf.x, y - hf.y);
    h = *(uint32_t*)&hb;
    l = *(uint32_t*)&lb;
}

#define SWZ(o) ((o) ^ (((o) >> 3) & 0x70))

// ---------------------------- tcgen05 helpers (guarded) ---------------------

#if defined(HAS_TCGEN05)

__device__ __forceinline__ uint32_t elect1() {
    uint32_t p;
    asm volatile("{ .reg .pred p; elect.sync _|p, 0xFFFFFFFF; selp.b32 %0,1,0,p; }"
                 : "=r"(p));
    return p;
}

#define TC_ALLOC(smem_addr, nCols) \
    asm volatile("tcgen05.alloc.cta_group::1.sync.aligned.shared::cta.b32 [%0], %1;" \
                 :: "r"((uint32_t)(smem_addr)), "r"((uint32_t)(nCols)) : "memory")
#define TC_DEALLOC(tmem, nCols) \
    asm volatile("tcgen05.dealloc.cta_group::1.sync.aligned.b32 %0, %1;" \
                 :: "r"(tmem), "r"((uint32_t)(nCols)))
#define TC_COMMIT(mbar) \
    asm volatile("tcgen05.commit.cta_group::1.mbarrier::arrive::one.shared::cluster.b64 [%0];" \
                 :: "r"((uint32_t)(mbar)) : "memory")
#define TC_WAIT_LD()      asm volatile("tcgen05.wait::ld.sync.aligned;" ::: "memory")
#define TC_FENCE_AFTER()  asm volatile("tcgen05.fence::after_thread_sync;" ::: "memory")
#define TC_FENCE_BEFORE() asm volatile("tcgen05.fence::before_thread_sync;" ::: "memory")
#define FENCE_ASYNC_SHARED() asm volatile("fence.proxy.async.shared::cta;" ::: "memory")
#define MB_INIT(mbar, cnt) \
    asm volatile("mbarrier.init.shared.b64 [%0], %1;" \
                 :: "r"((uint32_t)(mbar)), "r"((uint32_t)(cnt)) : "memory")
#define MB_INVAL(mbar) \
    asm volatile("mbarrier.inval.shared.b64 [%0];" :: "r"((uint32_t)(mbar)) : "memory")

#define MB_WAIT(mbar, parity) do {                                              \
    uint32_t _mb = (uint32_t)(mbar);                                            \
    uint32_t _ph = (uint32_t)(parity);                                          \
    uint32_t _done;                                                             \
    asm volatile("{\n\t.reg .pred p;\n\t"                                       \
        "mbarrier.try_wait.parity.acquire.cta.shared::cta.b64 p, [%1], %2;\n\t" \
        "selp.b32 %0, 1, 0, p;\n\t}"                                            \
        : "=r"(_done) : "r"(_mb), "r"(_ph) : "memory");                         \
    if (!_done) {                                                               \
        asm volatile("{\n\t.reg .pred P1;\n\t"                                  \
            "WL_%=:\n\t"                                                        \
            "mbarrier.try_wait.parity.acquire.cta.shared::cta.b64 P1, [%0], %1, 0x989680;\n\t" \
            "@P1 bra.uni WD_%=;\n\t"                                            \
            "bra.uni WL_%=;\n\t"                                                \
            "WD_%=:\n\t}"                                                       \
            :: "r"(_mb), "r"(_ph) : "memory");                                  \
    }                                                                           \
} while (0)

#define TC_LD_X32(r, addr) \
    asm volatile("tcgen05.ld.sync.aligned.32x32b.x32.b32 " \
        "{%0, %1, %2, %3, %4, %5, %6, %7, %8, %9, %10, %11, %12, %13, %14, %15, " \
        " %16, %17, %18, %19, %20, %21, %22, %23, %24, %25, %26, %27, %28, %29, %30, %31}, [%32];" \
        : "=r"((r)[0]), "=r"((r)[1]), "=r"((r)[2]), "=r"((r)[3]),               \
          "=r"((r)[4]), "=r"((r)[5]), "=r"((r)[6]), "=r"((r)[7]),               \
          "=r"((r)[8]), "=r"((r)[9]), "=r"((r)[10]), "=r"((r)[11]),             \
          "=r"((r)[12]), "=r"((r)[13]), "=r"((r)[14]), "=r"((r)[15]),           \
          "=r"((r)[16]), "=r"((r)[17]), "=r"((r)[18]), "=r"((r)[19]),           \
          "=r"((r)[20]), "=r"((r)[21]), "=r"((r)[22]), "=r"((r)[23]),           \
          "=r"((r)[24]), "=r"((r)[25]), "=r"((r)[26]), "=r"((r)[27]),           \
          "=r"((r)[28]), "=r"((r)[29]), "=r"((r)[30]), "=r"((r)[31])            \
        : "r"(addr))

__device__ __forceinline__ void tc_mma_f16(uint32_t d, uint64_t da, uint64_t db,
                                           uint32_t idesc, uint32_t en) {
    asm volatile("{\n\t.reg .pred p;\n\tsetp.ne.u32 p, %5, 0;\n\t"
                 "tcgen05.mma.cta_group::1.kind::f16 [%0], %1, %2, %3, {%4,%4,%4,%4}, p;\n\t}"
                 :: "r"(d), "l"(da), "l"(db), "r"(idesc), "r"(0u), "r"(en)
                 : "memory");
}

// SW128 K-major descriptor (layout=2, version=1, SBO=64, LBO=1)
static __device__ __forceinline__ uint64_t mk_desc(uint32_t addr) {
    return ((uint64_t)2 << 61) | ((uint64_t)1 << 46) | ((uint64_t)64 << 32) |
           ((uint64_t)1 << 16) | ((uint64_t)(addr >> 4) & 0x3FFF);
}

#endif  // HAS_TCGEN05

// ---------------------------- CSR build ------------------------------------

__global__ void k_hist(const int* __restrict__ dst, int* __restrict__ cnt, int e) {
    int i = blockIdx.x * blockDim.x + threadIdx.x;
    if (i < e) atomicAdd(&cnt[dst[i]], 1);
}

__global__ void k_scan_blk(const int* __restrict__ cnt, int* __restrict__ rows,
                           int* __restrict__ partial, float* __restrict__ dinv, int n) {
    __shared__ int sm[256];
    int t = threadIdx.x;
    int i = blockIdx.x * 256 + t;
    int v = (i < n) ? cnt[i] : 0;
    if (i < n) dinv[i] = rsqrtf((float)(v + 1));
    sm[t] = v;
    __syncthreads();
    #pragma unroll
    for (int off = 1; off < 256; off <<= 1) {
        int x = (t >= off) ? sm[t - off] : 0;
        __syncthreads();
        sm[t] += x;
        __syncthreads();
    }
    if (i < n) rows[i] = sm[t] - v;
    if (t == 255) partial[blockIdx.x] = sm[255];
}

__global__ void k_scan_add2(int* __restrict__ rows, int* __restrict__ pos,
                            const int* __restrict__ partial, int* __restrict__ cnt,
                            int n, int e_total) {
    __shared__ int sm[256];
    int t = threadIdx.x;
    int bid = blockIdx.x;
    sm[t] = (t < bid) ? partial[t] : 0;
    __syncthreads();
    #pragma unroll
    for (int off = 128; off >= 1; off >>= 1) {
        if (t < off) sm[t] += sm[t + off];
        __syncthreads();
    }
    int offv = sm[0];
    int i = bid * 256 + t;
    if (i < n) {
        int r = rows[i] + offv;
        rows[i] = r;
        pos[i] = r;
        cnt[i] = 0;
    }
    if (i == 0) rows[n] = e_total;
}

__global__ void k_scatter(const int* __restrict__ src, const int* __restrict__ dst,
                          const float* __restrict__ dinv, int* __restrict__ pos,
                          int* __restrict__ csr_src, float* __restrict__ csr_nrm, int e) {
    int i = blockIdx.x * blockDim.x + threadIdx.x;
    if (i >= e) return;
    int s = src[i], d = dst[i];
    int j = atomicAdd(&pos[d], 1);
    csr_src[j] = s;
    csr_nrm[j] = dinv[s] * dinv[d];
}

// ---------------------------- CSR aggregation -------------------------------

template <int F4PN, int RELU>
__global__ __launch_bounds__(256)
void k_csr_agg_split(const float4* __restrict__ X, const int* __restrict__ rows,
                     const int* __restrict__ csr_src, const float* __restrict__ csr_nrm,
                     const float* __restrict__ dinv, const float* __restrict__ bias,
                     uint2* __restrict__ hi, uint2* __restrict__ lo, int n, int npad) {
    const int NPB = 256 / F4PN;
    int tid = threadIdx.x;
    int local = tid / F4PN;
    int f4 = tid % F4PN;
    int i = blockIdx.x * NPB + local;
    if (i >= npad) return;
    size_t base = (size_t)i * F4PN + f4;
    if (i >= n) {
        hi[base] = make_uint2(0, 0);
        lo[base] = make_uint2(0, 0);
        return;
    }

    float d = dinv[i];
    float s = d * d;
    float4 xs = X[base];
    float4 acc;
    acc.x = xs.x * s; acc.y = xs.y * s; acc.z = xs.z * s; acc.w = xs.w * s;
    if (bias) {
        float4 b = ((const float4*)bias)[f4];
        acc.x += b.x; acc.y += b.y; acc.z += b.z; acc.w += b.w;
    }
    int beg = rows[i], end = rows[i + 1];
    for (int j = beg; j < end; j++) {
        float w = csr_nrm[j];
        float4 v = X[(size_t)csr_src[j] * F4PN + f4];
        acc.x = fmaf(w, v.x, acc.x);
        acc.y = fmaf(w, v.y, acc.y);
        acc.z = fmaf(w, v.z, acc.z);
        acc.w = fmaf(w, v.w, acc.w);
    }
    if (RELU) {
        acc.x = fmaxf(acc.x, 0.f); acc.y = fmaxf(acc.y, 0.f);
        acc.z = fmaxf(acc.z, 0.f); acc.w = fmaxf(acc.w, 0.f);
    }
    uint2 uh, ul;
    split2(acc.x, acc.y, uh.x, ul.x);
    split2(acc.z, acc.w, uh.y, ul.y);
    hi[base] = uh;
    lo[base] = ul;
}

// L4 aggregation (F=64, +b4) fused with relu + W5 matvec -> mv[i].
__global__ __launch_bounds__(256)
void k_csr_agg_mv(const float4* __restrict__ X, const int* __restrict__ rows,
                  const int* __restrict__ csr_src, const float* __restrict__ csr_nrm,
                  const float* __restrict__ dinv, const float* __restrict__ b4,
                  const float* __restrict__ W5, float* __restrict__ mv, int n) {
    int tid = threadIdx.x;
    int local = tid >> 4;
    int f4 = tid & 15;
    int i = blockIdx.x * 16 + local;
    bool valid = (i < n);
    int ii = valid ? i : 0;

    float d = dinv[ii];
    float s = d * d;
    size_t base = (size_t)ii * 16 + f4;
    float4 xs = X[base];
    float4 b = ((const float4*)b4)[f4];
    float4 acc;
    acc.x = fmaf(xs.x, s, b.x); acc.y = fmaf(xs.y, s, b.y);
    acc.z = fmaf(xs.z, s, b.z); acc.w = fmaf(xs.w, s, b.w);
    int beg = rows[ii], end = valid ? rows[ii + 1] : rows[ii];
    for (int j = beg; j < end; j++) {
        float w = csr_nrm[j];
        float4 v = X[(size_t)csr_src[j] * 16 + f4];
        acc.x = fmaf(w, v.x, acc.x);
        acc.y = fmaf(w, v.y, acc.y);
        acc.z = fmaf(w, v.z, acc.z);
        acc.w = fmaf(w, v.w, acc.w);
    }
    float4 w5 = ((const float4*)W5)[f4];
    float p = fmaxf(acc.x, 0.f) * w5.x + fmaxf(acc.y, 0.f) * w5.y +
              fmaxf(acc.z, 0.f) * w5.z + fmaxf(acc.w, 0.f) * w5.w;
    p += __shfl_xor_sync(0xffffffffu, p, 8, 16);
    p += __shfl_xor_sync(0xffffffffu, p, 4, 16);
    p += __shfl_xor_sync(0xffffffffu, p, 2, 16);
    p += __shfl_xor_sync(0xffffffffu, p, 1, 16);
    if (valid && f4 == 0) mv[i] = p;
}

__global__ void k_out_scalar(const float* __restrict__ mv, const int* __restrict__ rows,
                             const int* __restrict__ csr_src, const float* __restrict__ csr_nrm,
                             const float* __restrict__ dinv, const float* __restrict__ b5,
                             float* __restrict__ out, int n) {
    int i = blockIdx.x * blockDim.x + threadIdx.x;
    if (i >= n) return;
    float d = dinv[i];
    float s = b5[0] + d * d * mv[i];
    int beg = rows[i], end = rows[i + 1];
    for (int j = beg; j < end; j++)
        s = fmaf(csr_nrm[j], mv[csr_src[j]], s);
    out[i] = fmaxf(s, 0.0f);
}

// ---------------- batched tiled weight transpose + bf16 split ---------------

__global__ __launch_bounds__(256)
void k_wt_all(const float* __restrict__ W1, const float* __restrict__ W2,
              const float* __restrict__ W3, const float* __restrict__ W4,
              __nv_bfloat16* __restrict__ hi, __nv_bfloat16* __restrict__ lo) {
    __shared__ float tile[32][33];
    const float* W;
    int K, Nv, Npad;
    size_t off;
    switch (blockIdx.z) {
        case 0:  W = W1; K = 128;  Nv = 1024; Npad = 1024; off = WOFF1; break;
        case 1:  W = W2; K = 1024; Nv = 512;  Npad = 512;  off = WOFF2; break;
        case 2:  W = W3; K = 512;  Nv = 256;  Npad = 256;  off = WOFF3; break;
        default: W = W4; K = 256;  Nv = 64;   Npad = 128;  off = WOFF4; break;
    }
    int k0 = blockIdx.x * 32;
    int n0 = blockIdx.y * 32;
    if (k0 >= K || n0 >= Npad) return;
    int tx = threadIdx.x, ty = threadIdx.y;
    #pragma unroll
    for (int i = ty; i < 32; i += 8) {
        int k = k0 + i, n = n0 + tx;
        tile[i][tx] = (n < Nv) ? W[(size_t)k * Nv + n] : 0.0f;
    }
    __syncthreads();
    #pragma unroll
    for (int i = ty; i < 32; i += 8) {
        int n = n0 + i, k = k0 + tx;
        float v = tile[tx][i];
        __nv_bfloat16 h = __float2bfloat16(v);
        hi[off + (size_t)n * K + k] = h;
        lo[off + (size_t)n * K + k] = __float2bfloat16(v - __bfloat162float(h));
    }
}

// ---------------------- GEMM (dual-path) ------------------------------------
// C = A @ W; A bf16 hi/lo [Mpad,K] row-major; W bf16 hi/lo [Ncols][K] K-major.
// mode 0: fp32 out (stride Nout, cols < Nout). mode 2: bf16 hi/lo out
// (bias+relu), pad rows zeroed. Block 128 x BROWS column tile, 256 threads.

#define SROW 144
#define MMA_SMEM 221184

template <int BROWS, int NST>
__global__ __launch_bounds__(256, 1)
void k_mma_gemm(const __nv_bfloat16* __restrict__ Ah, const __nv_bfloat16* __restrict__ Al,
                const __nv_bfloat16* __restrict__ Bh, const __nv_bfloat16* __restrict__ Bl,
                const float* __restrict__ bias, float* __restrict__ C,
                __nv_bfloat16* __restrict__ Chi, __nv_bfloat16* __restrict__ Clo,
                int M, int K, int Nout, int mode) {
#if defined(HAS_TCGEN05)
    // ======================= tcgen05 path (sm_103a/f) =======================
    extern __shared__ char smem[];
    const uint32_t sb = smem_u32(smem);
    const int tid = threadIdx.x;
    const int wid = tid >> 5;
    const int lane = tid & 31;
    const int row0 = blockIdx.y * 128;
    const int col0 = blockIdx.x * BROWS;
    const int nc = K >> 6;

    const uint32_t ABYTES = 128 * 128;           // 16 KB per A array per stage
    const uint32_t BBYTES = BROWS * 128;         // 16/32 KB per B array
    const uint32_t oAl = ABYTES, oBh = 2 * ABYTES, oBl = 2 * ABYTES + BBYTES;
    const uint32_t STG = 2 * ABYTES + 2 * BBYTES;
    const uint32_t IDESC = (1u << 4) | (1u << 7) | (1u << 10) |
                           ((uint32_t)(BROWS / 8) << 17) | (8u << 24);

    if (tid == 0) { MB_INIT(sb + 8, 1); MB_INIT(sb + 16, 1); }
    if (wid == 0) TC_ALLOC(sb, 256);
    __syncthreads();
    uint32_t tmem;
    asm volatile("ld.shared.b32 %0, [%1];" : "=r"(tmem) : "r"(sb));

    auto loadc = [&](int t, int q) {
        size_t k0 = (size_t)t << 6;
        uint32_t st = sb + 1024 + q * STG;
        #pragma unroll
        for (int l = 0; l < 4; l++) {                 // A: 128 rows x 8 c16
            int idx = tid + l * 256;
            int r = idx >> 3, c = idx & 7;
            uint32_t o = SWZ((uint32_t)(r * 128 + c * 16));
            size_t g = (size_t)(row0 + r) * K + k0 + c * 8;
            cpa16(st + o, Ah + g);
            cpa16(st + oAl + o, Al + g);
        }
        #pragma unroll
        for (int l = 0; l < BROWS / 32; l++) {        // B: BROWS rows x 8 c16
            int idx = tid + l * 256;
            int r = idx >> 3, c = idx & 7;
            uint32_t o = SWZ((uint32_t)(r * 128 + c * 16));
            size_t g = (size_t)(col0 + r) * K + k0 + c * 8;
            cpa16(st + oBh + o, Bh + g);
            cpa16(st + oBl + o, Bl + g);
        }
        asm volatile("cp.async.commit_group;" ::: "memory");
    };

    loadc(0, 0);
    asm volatile("cp.async.wait_group 0;" ::: "memory");
    __syncthreads();
    FENCE_ASYNC_SHARED();

    for (int t = 0; t < nc; t++) {
        int p = t & 1;
        if (wid == 0) {
            TC_FENCE_AFTER();
            if (elect1()) {
                uint32_t st = sb + 1024 + p * STG;
                uint64_t dah = mk_desc(st);
                uint64_t dal = mk_desc(st + oAl);
                uint64_t dbh = mk_desc(st + oBh);
                uint64_t dbl = mk_desc(st + oBl);
                #pragma unroll
                for (int ks = 0; ks < 4; ks++) {
                    uint64_t o = (uint64_t)(ks * 2);
                    tc_mma_f16(tmem, dah + o, dbh + o, IDESC, !(t == 0 && ks == 0));
                    tc_mma_f16(tmem, dah + o, dbl + o, IDESC, 1);
                    tc_mma_f16(tmem, dal + o, dbh + o, IDESC, 1);
                }
                TC_COMMIT(sb + 8 + 8 * p);
            }
        }
        if (t + 1 < nc) {
            int q = (t + 1) & 1;
            if (t + 1 >= 2) {                      // buffer q last used by chunk t-1
                int ord = (t - 1 - q) >> 1;        // 0-based commit ordinal on q
                MB_WAIT(sb + 8 + 8 * q, ord & 1);
            }
            loadc(t + 1, q);
            asm volatile("cp.async.wait_group 0;" ::: "memory");
            __syncthreads();
            FENCE_ASYNC_SHARED();
        }
    }

    {
        int p = (nc - 1) & 1;
        int ord = ((nc - 1) - p) >> 1;
        MB_WAIT(sb + 8 + 8 * p, ord & 1);          // in-order MMA: last commit = all done
    }
    TC_FENCE_AFTER();

    // epilogue: warp w -> rows (w&3)*32+lane (TMEM subpartition), cols (w>>2) half
    {
        const int CPH = BROWS / 2;                 // cols per half (128 or 64)
        int half = wid >> 2, sub = wid & 3;
        int row = row0 + sub * 32 + lane;
        #pragma unroll
        for (int b = 0; b < CPH / 32; b++) {
            uint32_t regs[32];
            TC_LD_X32(regs, tmem + half * CPH + b * 32);
            TC_WAIT_LD();
            int cb = col0 + half * CPH + b * 32;
            if (mode == 2) {
                bool vr = (row < M);
                #pragma unroll
                for (int j = 0; j < 32; j += 2) {
                    float v0 = __uint_as_float(regs[j])     + bias[cb + j];
                    float v1 = __uint_as_float(regs[j + 1]) + bias[cb + j + 1];
                    v0 = fmaxf(v0, 0.f);
                    v1 = fmaxf(v1, 0.f);
                    uint32_t h, l;
                    split2(v0, v1, h, l);
                    if (!vr) { h = 0; l = 0; }
                    *(uint32_t*)&Chi[(size_t)row * Nout + cb + j] = h;
                    *(uint32_t*)&Clo[(size_t)row * Nout + cb + j] = l;
                }
            } else {
                if (row < M) {
                    #pragma unroll
                    for (int j = 0; j < 32; j++)
                        if (cb + j < Nout)
                            C[(size_t)row * Nout + cb + j] = __uint_as_float(regs[j]);
                }
            }
        }
    }
    TC_FENCE_BEFORE();
    __syncthreads();
    if (tid == 0) { MB_INVAL(sb + 8); MB_INVAL(sb + 16); }
    if (wid == 0) TC_DEALLOC(tmem, 256);
#else
    // ======================= mma.sync fallback (R14) ========================
    extern __shared__ char smem[];
    const uint32_t sb = smem_u32(smem);
    const int tid = threadIdx.x;
    const int wid = tid >> 5;
    const int lane = tid & 31;
    const int warp_m = wid & 3;
    const int warp_n = wid >> 2;
    const int row0 = blockIdx.y * 128;
    const int col0 = blockIdx.x * BROWS;
    const int nc = K >> 6;

    const int NT = BROWS / 16;
    const int HALVES = BROWS / 128;
    const uint32_t offAh = 0;
    const uint32_t offAl = 128 * SROW;
    const uint32_t offBh = 2 * 128 * SROW;
    const uint32_t offBl = 2 * 128 * SROW + BROWS * SROW;
    const uint32_t STAGE = 2 * 128 * SROW + 2 * BROWS * SROW;

    float acc[2][NT][4];
    #pragma unroll
    for (int i = 0; i < 2; i++)
        #pragma unroll
        for (int j = 0; j < NT; j++)
            #pragma unroll
            for (int c = 0; c < 4; c++) acc[i][j][c] = 0.0f;

    auto issue = [&](int t, int q) {
        size_t k0 = (size_t)t << 6;
        uint32_t st = sb + q * STAGE;
        #pragma unroll
        for (int l = 0; l < 4; l++) {
            int idx = tid + l * 256;
            int r = idx >> 3;
            int c = idx & 7;
            uint32_t o = (uint32_t)(r * SROW + c * 16);
            size_t ga = (size_t)(row0 + r) * K + k0 + c * 8;
            cpa16(st + offAh + o, Ah + ga);
            cpa16(st + offAl + o, Al + ga);
        }
        #pragma unroll
        for (int l = 0; l < BROWS / 32; l++) {
            int idx = tid + l * 256;
            int r = idx >> 3;
            int c = idx & 7;
            uint32_t o = (uint32_t)(r * SROW + c * 16);
            size_t gb = (size_t)(col0 + r) * K + k0 + c * 8;
            cpa16(st + offBh + o, Bh + gb);
            cpa16(st + offBl + o, Bl + gb);
        }
        asm volatile("cp.async.commit_group;" ::: "memory");
    };

    issue(0, 0);
    if (NST > 2 && nc > 1) issue(1, 1);

    int buf = 0;
    for (int t = 0; t < nc; t++) {
        if (NST > 2 && t + 1 < nc) {
            asm volatile("cp.async.wait_group 1;" ::: "memory");
        } else {
            asm volatile("cp.async.wait_group 0;" ::: "memory");
        }
        __syncthreads();
        if (t + NST - 1 < nc) issue(t + NST - 1, (t + NST - 1) % NST);

        uint32_t st = sb + buf * STAGE;
        #pragma unroll
        for (int ks = 0; ks < 4; ks++) {
            uint32_t ah[2][4], al[2][4];
            {
                uint32_t rr = (uint32_t)(warp_m * 32 + (lane & 15));
                uint32_t cc = (uint32_t)(ks * 16 + ((lane >> 4) << 3));
                #pragma unroll
                for (int mt = 0; mt < 2; mt++) {
                    uint32_t o = (rr + mt * 16) * SROW + cc * 2;
                    ldsm_x4(ah[mt], st + offAh + o);
                    ldsm_x4(al[mt], st + offAl + o);
                }
            }
            #pragma unroll
            for (int half = 0; half < HALVES; half++) {
                uint32_t bh[4][4], bl[4][4];
                {
                    int j = lane >> 3;
                    uint32_t nn = (uint32_t)(warp_n * (BROWS / 2) + half * 64 +
                                             ((j >> 1) << 3) + (lane & 7));
                    uint32_t kk = (uint32_t)(ks * 16 + ((j & 1) << 3));
                    #pragma unroll
                    for (int pp = 0; pp < 4; pp++) {
                        uint32_t o = (nn + pp * 16) * SROW + kk * 2;
                        ldsm_x4(bh[pp], st + offBh + o);
                        ldsm_x4(bl[pp], st + offBl + o);
                    }
                }
                #pragma unroll
                for (int mt = 0; mt < 2; mt++)
                    #pragma unroll
                    for (int ntl = 0; ntl < 8; ntl++) {
                        int nt = half * 8 + ntl;
                        const uint32_t* Bhf = &bh[ntl >> 1][(ntl & 1) * 2];
                        const uint32_t* Blf = &bl[ntl >> 1][(ntl & 1) * 2];
                        mma_bf16(acc[mt][nt], ah[mt], Bhf);
                        mma_bf16(acc[mt][nt], ah[mt], Blf);
                        mma_bf16(acc[mt][nt], al[mt], Bhf);
                    }
            }
        }
        buf = (buf + 1 == NST) ? 0 : buf + 1;
    }

    int gid = lane >> 2, tig = lane & 3;
    #pragma unroll
    for (int mt = 0; mt < 2; mt++) {
        int r0 = row0 + warp_m * 32 + mt * 16 + gid;
        #pragma unroll
        for (int nt = 0; nt < NT; nt++) {
            int cc = col0 + warp_n * (BROWS / 2) + nt * 8 + tig * 2;
            float2 v0 = make_float2(acc[mt][nt][0], acc[mt][nt][1]);
            float2 v1 = make_float2(acc[mt][nt][2], acc[mt][nt][3]);
            if (mode == 2) {
                float bx = bias[cc], by = bias[cc + 1];
                v0.x = fmaxf(v0.x + bx, 0.f); v0.y = fmaxf(v0.y + by, 0.f);
                v1.x = fmaxf(v1.x + bx, 0.f); v1.y = fmaxf(v1.y + by, 0.f);
                uint32_t h0, l0, h1, l1;
                split2(v0.x, v0.y, h0, l0);
                split2(v1.x, v1.y, h1, l1);
                if (r0 >= M) { h0 = l0 = 0; }
                if (r0 + 8 >= M) { h1 = l1 = 0; }
                *(uint32_t*)&Chi[(size_t)r0 * Nout + cc] = h0;
                *(uint32_t*)&Clo[(size_t)r0 * Nout + cc] = l0;
                *(uint32_t*)&Chi[(size_t)(r0 + 8) * Nout + cc] = h1;
                *(uint32_t*)&Clo[(size_t)(r0 + 8) * Nout + cc] = l1;
            } else {
                if (cc < Nout) {
                    if (r0 < M)     *(float2*)&C[(size_t)r0 * Nout + cc] = v0;
                    if (r0 + 8 < M) *(float2*)&C[(size_t)(r0 + 8) * Nout + cc] = v1;
                }
            }
        }
    }
#endif
}

// ---------------------------- launch ---------------------------------------

static inline unsigned blocks_for(size_t total, int threads) {
    return (unsigned)((total + threads - 1) / threads);
}

extern "C" void kernel_launch(void* const* d_in, const int* in_sizes, int n_in,
                              void* d_out, int out_size) {
    const float* x  = (const float*)d_in[0];
    const int*   ei = (const int*)d_in[1];
    const int N = in_sizes[0] / 128;
    const int E = in_sizes[1] / 2;
    const int* src = ei;
    const int* dst = ei + E;
    const float* W1 = (const float*)d_in[2];  const float* b1 = (const float*)d_in[3];
    const float* W2 = (const float*)d_in[4];  const float* b2 = (const float*)d_in[5];
    const float* W3 = (const float*)d_in[6];  const float* b3 = (const float*)d_in[7];
    const float* W4 = (const float*)d_in[8];  const float* b4 = (const float*)d_in[9];
    const float* W5 = (const float*)d_in[10]; const float* b5 = (const float*)d_in[11];
    float* out = (float*)d_out;

    float *bufA, *bufB, *dinv, *csr_nrm;
    int *cnt, *rows, *pos, *partial, *csr_src;
    __nv_bfloat16 *wthi, *wtlo, *ahi, *alo, *bhi, *blo;
    cudaGetSymbolAddress((void**)&bufA, g_bufA);
    cudaGetSymbolAddress((void**)&bufB, g_bufB);
    cudaGetSymbolAddress((void**)&dinv, g_dinv);
    cudaGetSymbolAddress((void**)&cnt, g_cnt);
    cudaGetSymbolAddress((void**)&rows, g_rows);
    cudaGetSymbolAddress((void**)&pos, g_pos);
    cudaGetSymbolAddress((void**)&partial, g_partial);
    cudaGetSymbolAddress((void**)&csr_src, g_csr_src);
    cudaGetSymbolAddress((void**)&csr_nrm, g_csr_nrm);
    cudaGetSymbolAddress((void**)&wthi, g_wthi);
    cudaGetSymbolAddress((void**)&wtlo, g_wtlo);
    cudaGetSymbolAddress((void**)&ahi, g_ahi);
    cudaGetSymbolAddress((void**)&alo, g_alo);
    cudaGetSymbolAddress((void**)&bhi, g_bhi);
    cudaGetSymbolAddress((void**)&blo, g_blo);

    cudaFuncSetAttribute(k_mma_gemm<256, 2>,
                         cudaFuncAttributeMaxDynamicSharedMemorySize, MMA_SMEM);
    cudaFuncSetAttribute(k_mma_gemm<128, 3>,
                         cudaFuncAttributeMaxDynamicSharedMemorySize, MMA_SMEM);

    const int T = 256;
    const int nblk = (N + 255) / 256;
    const int mtiles = (N + 127) / 128;
    const int Mpad = mtiles * 128;

    // ---- CSR build (cnt pre-zeroed by previous call / static init) ----
    k_hist<<<blocks_for(E, T), T>>>(dst, cnt, E);
    k_scan_blk<<<nblk, T>>>(cnt, rows, partial, dinv, N);
    k_scan_add2<<<nblk, T>>>(rows, pos, partial, cnt, N, E);
    k_scatter<<<blocks_for(E, T), T>>>(src, dst, dinv, pos, csr_src, csr_nrm, E);

    // ---- weight transposes (one launch) ----
    k_wt_all<<<dim3(32, 32, 4), dim3(32, 8)>>>(W1, W2, W3, W4, wthi, wtlo);

    // ---- Layer 1: CSR-agg of x -> ahi/alo [*,128]; GEMM 128->1024
    //      (b1+relu) -> bhi/blo ----
    k_csr_agg_split<32, 0><<<(Mpad + 7) / 8, 256>>>(
        (const float4*)x, rows, csr_src, csr_nrm, dinv, nullptr,
        (uint2*)ahi, (uint2*)alo, N, Mpad);
    k_mma_gemm<256, 2><<<dim3(1024 / 256, mtiles), 256, MMA_SMEM>>>(
        ahi, alo, wthi + WOFF1, wtlo + WOFF1, b1, nullptr, bhi, blo,
        N, 128, 1024, 2);

    // ---- Layer 2: GEMM 1024->512 -> bufA; CSR-agg (+b2, relu) -> ahi/alo ----
    k_mma_gemm<256, 2><<<dim3(512 / 256, mtiles), 256, MMA_SMEM>>>(
        bhi, blo, wthi + WOFF2, wtlo + WOFF2, nullptr, bufA, nullptr, nullptr,
        N, 1024, 512, 0);
    k_csr_agg_split<128, 1><<<(Mpad + 1) / 2, 256>>>(
        (const float4*)bufA, rows, csr_src, csr_nrm, dinv, b2,
        (uint2*)ahi, (uint2*)alo, N, Mpad);

    // ---- Layer 3: GEMM 512->256 -> bufA; CSR-agg (+b3, relu) -> ahi/alo ----
    k_mma_gemm<256, 2><<<dim3(1, mtiles), 256, MMA_SMEM>>>(
        ahi, alo, wthi + WOFF3, wtlo + WOFF3, nullptr, bufA, nullptr, nullptr,
        N, 512, 256, 0);
    k_csr_agg_split<64, 1><<<(Mpad + 3) / 4, 256>>>(
        (const float4*)bufA, rows, csr_src, csr_nrm, dinv, b3,
        (uint2*)ahi, (uint2*)alo, N, Mpad);

    // ---- Layer 4: GEMM 256->64 (weights padded to 128 cols) -> bufA;
    //      fused CSR-agg (+b4) + relu + W5 matvec -> bufB (mv) ----
    k_mma_gemm<128, 3><<<dim3(1, mtiles), 256, MMA_SMEM>>>(
        ahi, alo, wthi + WOFF4, wtlo + WOFF4, nullptr, bufA, nullptr, nullptr,
        N, 256, 64, 0);
    k_csr_agg_mv<<<(N + 15) / 16, 256>>>(
        (const float4*)bufA, rows, csr_src, csr_nrm, dinv, b4, W5, bufB, N);

    // ---- Layer 5 tail: scalar CSR-agg into out ----
    k_out_scalar<<<nblk, T>>>(bufB, rows, csr_src, csr_nrm, dinv, b5, out, N);
}

// round 17
// speedup vs baseline: 1.0206x; 1.0206x over previous
#include <cuda_runtime.h>
#include <cuda_bf16.h>
#include <cstddef>
#include <cstdint>

// ---------------------------------------------------------------------------
// ConvGraphNet (5-layer GCN) on GB300.
// R16: dual-path GEMM. tcgen05 path (sm_103a/f feature targets) now has REAL
//      double-buffering: two cp.async groups in flight, MMA t overlapped with
//      load t+1, buffer reuse gated on MMA-commit mbarrier. Fallback path =
//      proven R14 mma.sync bf16x3. All else identical to R14.
// ---------------------------------------------------------------------------

#if defined(__CUDA_ARCH__) && (defined(__CUDA_ARCH_FEAT_SM103_ALL) || \
    defined(__CUDA_ARCH_FEAT_SM100_ALL) || \
    (defined(__CUDA_ARCH_SPECIFIC__) && (__CUDA_ARCH_SPECIFIC__ >= 1000)) || \
    (defined(__CUDA_ARCH_FAMILY_SPECIFIC__) && (__CUDA_ARCH_FAMILY_SPECIFIC__ >= 1000)))
#define HAS_TCGEN05 1
#endif

#define NODES_MAX 50000
#define EDGES_MAX 400000
#define MPAD_MAX  50048   // 391 * 128

static __device__ float g_bufA[(size_t)NODES_MAX * 1024];
static __device__ float g_bufB[(size_t)NODES_MAX * 1024];
static __device__ float g_dinv[NODES_MAX];
static __device__ int   g_cnt[NODES_MAX];
static __device__ int   g_rows[NODES_MAX + 1];
static __device__ int   g_pos[NODES_MAX];
static __device__ int   g_partial[256];
static __device__ int   g_csr_src[EDGES_MAX];
static __device__ float g_csr_nrm[EDGES_MAX];
static __device__ __nv_bfloat16 g_wthi[1 << 20];
static __device__ __nv_bfloat16 g_wtlo[1 << 20];
static __device__ __nv_bfloat16 g_ahi[(size_t)MPAD_MAX * 512];
static __device__ __nv_bfloat16 g_alo[(size_t)MPAD_MAX * 512];
static __device__ __nv_bfloat16 g_bhi[(size_t)MPAD_MAX * 1024];
static __device__ __nv_bfloat16 g_blo[(size_t)MPAD_MAX * 1024];

// weight-transpose regions inside g_wthi/g_wtlo
#define WOFF1 0          // W1t: 1024 x 128
#define WOFF2 131072     // W2t: 512 x 1024
#define WOFF3 655360     // W3t: 256 x 512
#define WOFF4 786432     // W4t: 128 x 256 (cols 64..127 zero)

// ---------------------------- common helpers --------------------------------

__device__ __forceinline__ uint32_t smem_u32(const void* p) {
    uint32_t a;
    asm("{ .reg .u64 t; cvta.to.shared.u64 t, %1; cvt.u32.u64 %0, t; }"
        : "=r"(a) : "l"(p));
    return a;
}

__device__ __forceinline__ void cpa16(uint32_t s, const void* g) {
    asm volatile("cp.async.cg.shared.global [%0], [%1], 16;" :: "r"(s), "l"(g));
}

__device__ __forceinline__ void ldsm_x4(uint32_t* r, uint32_t addr) {
    asm volatile("ldmatrix.sync.aligned.m8n8.x4.shared.b16 {%0,%1,%2,%3}, [%4];"
                 : "=r"(r[0]), "=r"(r[1]), "=r"(r[2]), "=r"(r[3]) : "r"(addr));
}

__device__ __forceinline__ void mma_bf16(float* d, const uint32_t* a, const uint32_t* b) {
    asm volatile("mma.sync.aligned.m16n8k16.row.col.f32.bf16.bf16.f32 "
                 "{%0,%1,%2,%3}, {%4,%5,%6,%7}, {%8,%9}, {%0,%1,%2,%3};"
                 : "+f"(d[0]), "+f"(d[1]), "+f"(d[2]), "+f"(d[3])
                 : "r"(a[0]), "r"(a[1]), "r"(a[2]), "r"(a[3]), "r"(b[0]), "r"(b[1]));
}

__device__ __forceinline__ void split2(float x, float y, uint32_t& h, uint32_t& l) {
    __nv_bfloat162 hb = __floats2bfloat162_rn(x, y);
    float2 hf = __bfloat1622float2(hb);
    __nv_bfloat162 lb = __floats2bfloat162_rn(x - hf.x, y - hf.y);
    h = *(uint32_t*)&hb;
    l = *(uint32_t*)&lb;
}

#define SWZ(o) ((o) ^ (((o) >> 3) & 0x70))

// ---------------------------- tcgen05 helpers (guarded) ---------------------

#if defined(HAS_TCGEN05)

__device__ __forceinline__ uint32_t elect1() {
    uint32_t p;
    asm volatile("{ .reg .pred p; elect.sync _|p, 0xFFFFFFFF; selp.b32 %0,1,0,p; }"
                 : "=r"(p));
    return p;
}

#define TC_ALLOC(smem_addr, nCols) \
    asm volatile("tcgen05.alloc.cta_group::1.sync.aligned.shared::cta.b32 [%0], %1;" \
                 :: "r"((uint32_t)(smem_addr)), "r"((uint32_t)(nCols)) : "memory")
#define TC_DEALLOC(tmem, nCols) \
    asm volatile("tcgen05.dealloc.cta_group::1.sync.aligned.b32 %0, %1;" \
                 :: "r"(tmem), "r"((uint32_t)(nCols)))
#define TC_COMMIT(mbar) \
    asm volatile("tcgen05.commit.cta_group::1.mbarrier::arrive::one.shared::cluster.b64 [%0];" \
                 :: "r"((uint32_t)(mbar)) : "memory")
#define TC_WAIT_LD()      asm volatile("tcgen05.wait::ld.sync.aligned;" ::: "memory")
#define TC_FENCE_AFTER()  asm volatile("tcgen05.fence::after_thread_sync;" ::: "memory")
#define TC_FENCE_BEFORE() asm volatile("tcgen05.fence::before_thread_sync;" ::: "memory")
#define FENCE_ASYNC_SHARED() asm volatile("fence.proxy.async.shared::cta;" ::: "memory")
#define MB_INIT(mbar, cnt) \
    asm volatile("mbarrier.init.shared.b64 [%0], %1;" \
                 :: "r"((uint32_t)(mbar)), "r"((uint32_t)(cnt)) : "memory")
#define MB_INVAL(mbar) \
    asm volatile("mbarrier.inval.shared.b64 [%0];" :: "r"((uint32_t)(mbar)) : "memory")

#define MB_WAIT(mbar, parity) do {                                              \
    uint32_t _mb = (uint32_t)(mbar);                                            \
    uint32_t _ph = (uint32_t)(parity);                                          \
    uint32_t _done;                                                             \
    asm volatile("{\n\t.reg .pred p;\n\t"                                       \
        "mbarrier.try_wait.parity.acquire.cta.shared::cta.b64 p, [%1], %2;\n\t" \
        "selp.b32 %0, 1, 0, p;\n\t}"                                            \
        : "=r"(_done) : "r"(_mb), "r"(_ph) : "memory");                         \
    if (!_done) {                                                               \
        asm volatile("{\n\t.reg .pred P1;\n\t"                                  \
            "WL_%=:\n\t"                                                        \
            "mbarrier.try_wait.parity.acquire.cta.shared::cta.b64 P1, [%0], %1, 0x989680;\n\t" \
            "@P1 bra.uni WD_%=;\n\t"                                            \
            "bra.uni WL_%=;\n\t"                                                \
            "WD_%=:\n\t}"                                                       \
            :: "r"(_mb), "r"(_ph) : "memory");                                  \
    }                                                                           \
} while (0)

#define TC_LD_X32(r, addr) \
    asm volatile("tcgen05.ld.sync.aligned.32x32b.x32.b32 " \
        "{%0, %1, %2, %3, %4, %5, %6, %7, %8, %9, %10, %11, %12, %13, %14, %15, " \
        " %16, %17, %18, %19, %20, %21, %22, %23, %24, %25, %26, %27, %28, %29, %30, %31}, [%32];" \
        : "=r"((r)[0]), "=r"((r)[1]), "=r"((r)[2]), "=r"((r)[3]),               \
          "=r"((r)[4]), "=r"((r)[5]), "=r"((r)[6]), "=r"((r)[7]),               \
          "=r"((r)[8]), "=r"((r)[9]), "=r"((r)[10]), "=r"((r)[11]),             \
          "=r"((r)[12]), "=r"((r)[13]), "=r"((r)[14]), "=r"((r)[15]),           \
          "=r"((r)[16]), "=r"((r)[17]), "=r"((r)[18]), "=r"((r)[19]),           \
          "=r"((r)[20]), "=r"((r)[21]), "=r"((r)[22]), "=r"((r)[23]),           \
          "=r"((r)[24]), "=r"((r)[25]), "=r"((r)[26]), "=r"((r)[27]),           \
          "=r"((r)[28]), "=r"((r)[29]), "=r"((r)[30]), "=r"((r)[31])            \
        : "r"(addr))

__device__ __forceinline__ void tc_mma_f16(uint32_t d, uint64_t da, uint64_t db,
                                           uint32_t idesc, uint32_t en) {
    asm volatile("{\n\t.reg .pred p;\n\tsetp.ne.u32 p, %5, 0;\n\t"
                 "tcgen05.mma.cta_group::1.kind::f16 [%0], %1, %2, %3, {%4,%4,%4,%4}, p;\n\t}"
                 :: "r"(d), "l"(da), "l"(db), "r"(idesc), "r"(0u), "r"(en)
                 : "memory");
}

// SW128 K-major descriptor (layout=2, version=1, SBO=64, LBO=1)
static __device__ __forceinline__ uint64_t mk_desc(uint32_t addr) {
    return ((uint64_t)2 << 61) | ((uint64_t)1 << 46) | ((uint64_t)64 << 32) |
           ((uint64_t)1 << 16) | ((uint64_t)(addr >> 4) & 0x3FFF);
}

#endif  // HAS_TCGEN05

// ---------------------------- CSR build ------------------------------------

__global__ void k_hist(const int* __restrict__ dst, int* __restrict__ cnt, int e) {
    int i = blockIdx.x * blockDim.x + threadIdx.x;
    if (i < e) atomicAdd(&cnt[dst[i]], 1);
}

__global__ void k_scan_blk(const int* __restrict__ cnt, int* __restrict__ rows,
                           int* __restrict__ partial, float* __restrict__ dinv, int n) {
    __shared__ int sm[256];
    int t = threadIdx.x;
    int i = blockIdx.x * 256 + t;
    int v = (i < n) ? cnt[i] : 0;
    if (i < n) dinv[i] = rsqrtf((float)(v + 1));
    sm[t] = v;
    __syncthreads();
    #pragma unroll
    for (int off = 1; off < 256; off <<= 1) {
        int x = (t >= off) ? sm[t - off] : 0;
        __syncthreads();
        sm[t] += x;
        __syncthreads();
    }
    if (i < n) rows[i] = sm[t] - v;
    if (t == 255) partial[blockIdx.x] = sm[255];
}

__global__ void k_scan_add2(int* __restrict__ rows, int* __restrict__ pos,
                            const int* __restrict__ partial, int* __restrict__ cnt,
                            int n, int e_total) {
    __shared__ int sm[256];
    int t = threadIdx.x;
    int bid = blockIdx.x;
    sm[t] = (t < bid) ? partial[t] : 0;
    __syncthreads();
    #pragma unroll
    for (int off = 128; off >= 1; off >>= 1) {
        if (t < off) sm[t] += sm[t + off];
        __syncthreads();
    }
    int offv = sm[0];
    int i = bid * 256 + t;
    if (i < n) {
        int r = rows[i] + offv;
        rows[i] = r;
        pos[i] = r;
        cnt[i] = 0;
    }
    if (i == 0) rows[n] = e_total;
}

__global__ void k_scatter(const int* __restrict__ src, const int* __restrict__ dst,
                          const float* __restrict__ dinv, int* __restrict__ pos,
                          int* __restrict__ csr_src, float* __restrict__ csr_nrm, int e) {
    int i = blockIdx.x * blockDim.x + threadIdx.x;
    if (i >= e) return;
    int s = src[i], d = dst[i];
    int j = atomicAdd(&pos[d], 1);
    csr_src[j] = s;
    csr_nrm[j] = dinv[s] * dinv[d];
}

// ---------------------------- CSR aggregation -------------------------------

template <int F4PN, int RELU>
__global__ __launch_bounds__(256)
void k_csr_agg_split(const float4* __restrict__ X, const int* __restrict__ rows,
                     const int* __restrict__ csr_src, const float* __restrict__ csr_nrm,
                     const float* __restrict__ dinv, const float* __restrict__ bias,
                     uint2* __restrict__ hi, uint2* __restrict__ lo, int n, int npad) {
    const int NPB = 256 / F4PN;
    int tid = threadIdx.x;
    int local = tid / F4PN;
    int f4 = tid % F4PN;
    int i = blockIdx.x * NPB + local;
    if (i >= npad) return;
    size_t base = (size_t)i * F4PN + f4;
    if (i >= n) {
        hi[base] = make_uint2(0, 0);
        lo[base] = make_uint2(0, 0);
        return;
    }

    float d = dinv[i];
    float s = d * d;
    float4 xs = X[base];
    float4 acc;
    acc.x = xs.x * s; acc.y = xs.y * s; acc.z = xs.z * s; acc.w = xs.w * s;
    if (bias) {
        float4 b = ((const float4*)bias)[f4];
        acc.x += b.x; acc.y += b.y; acc.z += b.z; acc.w += b.w;
    }
    int beg = rows[i], end = rows[i + 1];
    for (int j = beg; j < end; j++) {
        float w = csr_nrm[j];
        float4 v = X[(size_t)csr_src[j] * F4PN + f4];
        acc.x = fmaf(w, v.x, acc.x);
        acc.y = fmaf(w, v.y, acc.y);
        acc.z = fmaf(w, v.z, acc.z);
        acc.w = fmaf(w, v.w, acc.w);
    }
    if (RELU) {
        acc.x = fmaxf(acc.x, 0.f); acc.y = fmaxf(acc.y, 0.f);
        acc.z = fmaxf(acc.z, 0.f); acc.w = fmaxf(acc.w, 0.f);
    }
    uint2 uh, ul;
    split2(acc.x, acc.y, uh.x, ul.x);
    split2(acc.z, acc.w, uh.y, ul.y);
    hi[base] = uh;
    lo[base] = ul;
}

// L4 aggregation (F=64, +b4) fused with relu + W5 matvec -> mv[i].
__global__ __launch_bounds__(256)
void k_csr_agg_mv(const float4* __restrict__ X, const int* __restrict__ rows,
                  const int* __restrict__ csr_src, const float* __restrict__ csr_nrm,
                  const float* __restrict__ dinv, const float* __restrict__ b4,
                  const float* __restrict__ W5, float* __restrict__ mv, int n) {
    int tid = threadIdx.x;
    int local = tid >> 4;
    int f4 = tid & 15;
    int i = blockIdx.x * 16 + local;
    bool valid = (i < n);
    int ii = valid ? i : 0;

    float d = dinv[ii];
    float s = d * d;
    size_t base = (size_t)ii * 16 + f4;
    float4 xs = X[base];
    float4 b = ((const float4*)b4)[f4];
    float4 acc;
    acc.x = fmaf(xs.x, s, b.x); acc.y = fmaf(xs.y, s, b.y);
    acc.z = fmaf(xs.z, s, b.z); acc.w = fmaf(xs.w, s, b.w);
    int beg = rows[ii], end = valid ? rows[ii + 1] : rows[ii];
    for (int j = beg; j < end; j++) {
        float w = csr_nrm[j];
        float4 v = X[(size_t)csr_src[j] * 16 + f4];
        acc.x = fmaf(w, v.x, acc.x);
        acc.y = fmaf(w, v.y, acc.y);
        acc.z = fmaf(w, v.z, acc.z);
        acc.w = fmaf(w, v.w, acc.w);
    }
    float4 w5 = ((const float4*)W5)[f4];
    float p = fmaxf(acc.x, 0.f) * w5.x + fmaxf(acc.y, 0.f) * w5.y +
              fmaxf(acc.z, 0.f) * w5.z + fmaxf(acc.w, 0.f) * w5.w;
    p += __shfl_xor_sync(0xffffffffu, p, 8, 16);
    p += __shfl_xor_sync(0xffffffffu, p, 4, 16);
    p += __shfl_xor_sync(0xffffffffu, p, 2, 16);
    p += __shfl_xor_sync(0xffffffffu, p, 1, 16);
    if (valid && f4 == 0) mv[i] = p;
}

__global__ void k_out_scalar(const float* __restrict__ mv, const int* __restrict__ rows,
                             const int* __restrict__ csr_src, const float* __restrict__ csr_nrm,
                             const float* __restrict__ dinv, const float* __restrict__ b5,
                             float* __restrict__ out, int n) {
    int i = blockIdx.x * blockDim.x + threadIdx.x;
    if (i >= n) return;
    float d = dinv[i];
    float s = b5[0] + d * d * mv[i];
    int beg = rows[i], end = rows[i + 1];
    for (int j = beg; j < end; j++)
        s = fmaf(csr_nrm[j], mv[csr_src[j]], s);
    out[i] = fmaxf(s, 0.0f);
}

// ---------------- batched tiled weight transpose + bf16 split ---------------

__global__ __launch_bounds__(256)
void k_wt_all(const float* __restrict__ W1, const float* __restrict__ W2,
              const float* __restrict__ W3, const float* __restrict__ W4,
              __nv_bfloat16* __restrict__ hi, __nv_bfloat16* __restrict__ lo) {
    __shared__ float tile[32][33];
    const float* W;
    int K, Nv, Npad;
    size_t off;
    switch (blockIdx.z) {
        case 0:  W = W1; K = 128;  Nv = 1024; Npad = 1024; off = WOFF1; break;
        case 1:  W = W2; K = 1024; Nv = 512;  Npad = 512;  off = WOFF2; break;
        case 2:  W = W3; K = 512;  Nv = 256;  Npad = 256;  off = WOFF3; break;
        default: W = W4; K = 256;  Nv = 64;   Npad = 128;  off = WOFF4; break;
    }
    int k0 = blockIdx.x * 32;
    int n0 = blockIdx.y * 32;
    if (k0 >= K || n0 >= Npad) return;
    int tx = threadIdx.x, ty = threadIdx.y;
    #pragma unroll
    for (int i = ty; i < 32; i += 8) {
        int k = k0 + i, n = n0 + tx;
        tile[i][tx] = (n < Nv) ? W[(size_t)k * Nv + n] : 0.0f;
    }
    __syncthreads();
    #pragma unroll
    for (int i = ty; i < 32; i += 8) {
        int n = n0 + i, k = k0 + tx;
        float v = tile[tx][i];
        __nv_bfloat16 h = __float2bfloat16(v);
        hi[off + (size_t)n * K + k] = h;
        lo[off + (size_t)n * K + k] = __float2bfloat16(v - __bfloat162float(h));
    }
}

// ---------------------- GEMM (dual-path) ------------------------------------
// C = A @ W; A bf16 hi/lo [Mpad,K] row-major; W bf16 hi/lo [Ncols][K] K-major.
// mode 0: fp32 out (stride Nout, cols < Nout). mode 2: bf16 hi/lo out
// (bias+relu), pad rows zeroed. Block 128 x BROWS column tile, 256 threads.

#define SROW 144
#define MMA_SMEM 221184

template <int BROWS, int NST>
__global__ __launch_bounds__(256, 1)
void k_mma_gemm(const __nv_bfloat16* __restrict__ Ah, const __nv_bfloat16* __restrict__ Al,
                const __nv_bfloat16* __restrict__ Bh, const __nv_bfloat16* __restrict__ Bl,
                const float* __restrict__ bias, float* __restrict__ C,
                __nv_bfloat16* __restrict__ Chi, __nv_bfloat16* __restrict__ Clo,
                int M, int K, int Nout, int mode) {
#if defined(HAS_TCGEN05)
    // ======================= tcgen05 path (sm_103a/f) =======================
    extern __shared__ char smem[];
    const uint32_t sb = smem_u32(smem);
    const int tid = threadIdx.x;
    const int wid = tid >> 5;
    const int lane = tid & 31;
    const int row0 = blockIdx.y * 128;
    const int col0 = blockIdx.x * BROWS;
    const int nc = K >> 6;

    const uint32_t ABYTES = 128 * 128;           // 16 KB per A array per stage
    const uint32_t BBYTES = BROWS * 128;         // 16/32 KB per B array
    const uint32_t oAl = ABYTES, oBh = 2 * ABYTES, oBl = 2 * ABYTES + BBYTES;
    const uint32_t STG = 2 * ABYTES + 2 * BBYTES;
    const uint32_t IDESC = (1u << 4) | (1u << 7) | (1u << 10) |
                           ((uint32_t)(BROWS / 8) << 17) | (8u << 24);

    if (tid == 0) { MB_INIT(sb + 8, 1); MB_INIT(sb + 16, 1); }
    if (wid == 0) TC_ALLOC(sb, 256);
    __syncthreads();
    uint32_t tmem;
    asm volatile("ld.shared.b32 %0, [%1];" : "=r"(tmem) : "r"(sb));

    auto loadc = [&](int t, int q) {
        size_t k0 = (size_t)t << 6;
        uint32_t st = sb + 1024 + q * STG;
        #pragma unroll
        for (int l = 0; l < 4; l++) {                 // A: 128 rows x 8 c16
            int idx = tid + l * 256;
            int r = idx >> 3, c = idx & 7;
            uint32_t o = SWZ((uint32_t)(r * 128 + c * 16));
            size_t g = (size_t)(row0 + r) * K + k0 + c * 8;
            cpa16(st + o, Ah + g);
            cpa16(st + oAl + o, Al + g);
        }
        #pragma unroll
        for (int l = 0; l < BROWS / 32; l++) {        // B: BROWS rows x 8 c16
            int idx = tid + l * 256;
            int r = idx >> 3, c = idx & 7;
            uint32_t o = SWZ((uint32_t)(r * 128 + c * 16));
            size_t g = (size_t)(col0 + r) * K + k0 + c * 8;
            cpa16(st + oBh + o, Bh + g);
            cpa16(st + oBl + o, Bl + g);
        }
        asm volatile("cp.async.commit_group;" ::: "memory");
    };

    // Two chunks in flight from the start.
    loadc(0, 0);
    if (nc > 1) loadc(1, 1);

    for (int t = 0; t < nc; t++) {
        int p = t & 1;
        if (t + 1 < nc) {
            asm volatile("cp.async.wait_group 1;" ::: "memory");   // chunk t ready
        } else {
            asm volatile("cp.async.wait_group 0;" ::: "memory");
        }
        __syncthreads();
        FENCE_ASYNC_SHARED();

        if (wid == 0) {
            TC_FENCE_AFTER();
            if (elect1()) {
                uint32_t st = sb + 1024 + p * STG;
                uint64_t dah = mk_desc(st);
                uint64_t dal = mk_desc(st + oAl);
                uint64_t dbh = mk_desc(st + oBh);
                uint64_t dbl = mk_desc(st + oBl);
                #pragma unroll
                for (int ks = 0; ks < 4; ks++) {
                    uint64_t o = (uint64_t)(ks * 2);
                    tc_mma_f16(tmem, dah + o, dbh + o, IDESC, !(t == 0 && ks == 0));
                    tc_mma_f16(tmem, dah + o, dbl + o, IDESC, 1);
                    tc_mma_f16(tmem, dal + o, dbh + o, IDESC, 1);
                }
                TC_COMMIT(sb + 8 + 8 * p);
            }
        }

        // Refill buffer p with chunk t+2 once MMA t (its last reader) is done.
        // Meanwhile chunk t+1's load is already in flight -> MMA t overlaps it.
        if (t + 2 < nc) {
            MB_WAIT(sb + 8 + 8 * p, ((t - p) >> 1) & 1);   // commit ordinal parity
            loadc(t + 2, p);
        }
    }

    {   // final MMA completion (in-order commits)
        int p = (nc - 1) & 1;
        MB_WAIT(sb + 8 + 8 * p, (((nc - 1) - p) >> 1) & 1);
    }
    TC_FENCE_AFTER();

    // epilogue: warp w -> rows (w&3)*32+lane (TMEM subpartition), cols (w>>2) half
    {
        const int CPH = BROWS / 2;                 // cols per half (128 or 64)
        int half = wid >> 2, sub = wid & 3;
        int row = row0 + sub * 32 + lane;
        #pragma unroll
        for (int b = 0; b < CPH / 32; b++) {
            uint32_t regs[32];
            TC_LD_X32(regs, tmem + half * CPH + b * 32);
            TC_WAIT_LD();
            int cb = col0 + half * CPH + b * 32;
            if (mode == 2) {
                bool vr = (row < M);
                #pragma unroll
                for (int j = 0; j < 32; j += 2) {
                    float v0 = __uint_as_float(regs[j])     + bias[cb + j];
                    float v1 = __uint_as_float(regs[j + 1]) + bias[cb + j + 1];
                    v0 = fmaxf(v0, 0.f);
                    v1 = fmaxf(v1, 0.f);
                    uint32_t h, l;
                    split2(v0, v1, h, l);
                    if (!vr) { h = 0; l = 0; }
                    *(uint32_t*)&Chi[(size_t)row * Nout + cb + j] = h;
                    *(uint32_t*)&Clo[(size_t)row * Nout + cb + j] = l;
                }
            } else {
                if (row < M) {
                    #pragma unroll
                    for (int j = 0; j < 32; j++)
                        if (cb + j < Nout)
                            C[(size_t)row * Nout + cb + j] = __uint_as_float(regs[j]);
                }
            }
        }
    }
    TC_FENCE_BEFORE();
    __syncthreads();
    if (tid == 0) { MB_INVAL(sb + 8); MB_INVAL(sb + 16); }
    if (wid == 0) TC_DEALLOC(tmem, 256);
#else
    // ======================= mma.sync fallback (R14) ========================
    extern __shared__ char smem[];
    const uint32_t sb = smem_u32(smem);
    const int tid = threadIdx.x;
    const int wid = tid >> 5;
    const int lane = tid & 31;
    const int warp_m = wid & 3;
    const int warp_n = wid >> 2;
    const int row0 = blockIdx.y * 128;
    const int col0 = blockIdx.x * BROWS;
    const int nc = K >> 6;

    const int NT = BROWS / 16;
    const int HALVES = BROWS / 128;
    const uint32_t offAh = 0;
    const uint32_t offAl = 128 * SROW;
    const uint32_t offBh = 2 * 128 * SROW;
    const uint32_t offBl = 2 * 128 * SROW + BROWS * SROW;
    const uint32_t STAGE = 2 * 128 * SROW + 2 * BROWS * SROW;

    float acc[2][NT][4];
    #pragma unroll
    for (int i = 0; i < 2; i++)
        #pragma unroll
        for (int j = 0; j < NT; j++)
            #pragma unroll
            for (int c = 0; c < 4; c++) acc[i][j][c] = 0.0f;

    auto issue = [&](int t, int q) {
        size_t k0 = (size_t)t << 6;
        uint32_t st = sb + q * STAGE;
        #pragma unroll
        for (int l = 0; l < 4; l++) {
            int idx = tid + l * 256;
            int r = idx >> 3;
            int c = idx & 7;
            uint32_t o = (uint32_t)(r * SROW + c * 16);
            size_t ga = (size_t)(row0 + r) * K + k0 + c * 8;
            cpa16(st + offAh + o, Ah + ga);
            cpa16(st + offAl + o, Al + ga);
        }
        #pragma unroll
        for (int l = 0; l < BROWS / 32; l++) {
            int idx = tid + l * 256;
            int r = idx >> 3;
            int c = idx & 7;
            uint32_t o = (uint32_t)(r * SROW + c * 16);
            size_t gb = (size_t)(col0 + r) * K + k0 + c * 8;
            cpa16(st + offBh + o, Bh + gb);
            cpa16(st + offBl + o, Bl + gb);
        }
        asm volatile("cp.async.commit_group;" ::: "memory");
    };

    issue(0, 0);
    if (NST > 2 && nc > 1) issue(1, 1);

    int buf = 0;
    for (int t = 0; t < nc; t++) {
        if (NST > 2 && t + 1 < nc) {
            asm volatile("cp.async.wait_group 1;" ::: "memory");
        } else {
            asm volatile("cp.async.wait_group 0;" ::: "memory");
        }
        __syncthreads();
        if (t + NST - 1 < nc) issue(t + NST - 1, (t + NST - 1) % NST);

        uint32_t st = sb + buf * STAGE;
        #pragma unroll
        for (int ks = 0; ks < 4; ks++) {
            uint32_t ah[2][4], al[2][4];
            {
                uint32_t rr = (uint32_t)(warp_m * 32 + (lane & 15));
                uint32_t cc = (uint32_t)(ks * 16 + ((lane >> 4) << 3));
                #pragma unroll
                for (int mt = 0; mt < 2; mt++) {
                    uint32_t o = (rr + mt * 16) * SROW + cc * 2;
                    ldsm_x4(ah[mt], st + offAh + o);
                    ldsm_x4(al[mt], st + offAl + o);
                }
            }
            #pragma unroll
            for (int half = 0; half < HALVES; half++) {
                uint32_t bh[4][4], bl[4][4];
                {
                    int j = lane >> 3;
                    uint32_t nn = (uint32_t)(warp_n * (BROWS / 2) + half * 64 +
                                             ((j >> 1) << 3) + (lane & 7));
                    uint32_t kk = (uint32_t)(ks * 16 + ((j & 1) << 3));
                    #pragma unroll
                    for (int pp = 0; pp < 4; pp++) {
                        uint32_t o = (nn + pp * 16) * SROW + kk * 2;
                        ldsm_x4(bh[pp], st + offBh + o);
                        ldsm_x4(bl[pp], st + offBl + o);
                    }
                }
                #pragma unroll
                for (int mt = 0; mt < 2; mt++)
                    #pragma unroll
                    for (int ntl = 0; ntl < 8; ntl++) {
                        int nt = half * 8 + ntl;
                        const uint32_t* Bhf = &bh[ntl >> 1][(ntl & 1) * 2];
                        const uint32_t* Blf = &bl[ntl >> 1][(ntl & 1) * 2];
                        mma_bf16(acc[mt][nt], ah[mt], Bhf);
                        mma_bf16(acc[mt][nt], ah[mt], Blf);
                        mma_bf16(acc[mt][nt], al[mt], Bhf);
                    }
            }
        }
        buf = (buf + 1 == NST) ? 0 : buf + 1;
    }

    int gid = lane >> 2, tig = lane & 3;
    #pragma unroll
    for (int mt = 0; mt < 2; mt++) {
        int r0 = row0 + warp_m * 32 + mt * 16 + gid;
        #pragma unroll
        for (int nt = 0; nt < NT; nt++) {
            int cc = col0 + warp_n * (BROWS / 2) + nt * 8 + tig * 2;
            float2 v0 = make_float2(acc[mt][nt][0], acc[mt][nt][1]);
            float2 v1 = make_float2(acc[mt][nt][2], acc[mt][nt][3]);
            if (mode == 2) {
                float bx = bias[cc], by = bias[cc + 1];
                v0.x = fmaxf(v0.x + bx, 0.f); v0.y = fmaxf(v0.y + by, 0.f);
                v1.x = fmaxf(v1.x + bx, 0.f); v1.y = fmaxf(v1.y + by, 0.f);
                uint32_t h0, l0, h1, l1;
                split2(v0.x, v0.y, h0, l0);
                split2(v1.x, v1.y, h1, l1);
                if (r0 >= M) { h0 = l0 = 0; }
                if (r0 + 8 >= M) { h1 = l1 = 0; }
                *(uint32_t*)&Chi[(size_t)r0 * Nout + cc] = h0;
                *(uint32_t*)&Clo[(size_t)r0 * Nout + cc] = l0;
                *(uint32_t*)&Chi[(size_t)(r0 + 8) * Nout + cc] = h1;
                *(uint32_t*)&Clo[(size_t)(r0 + 8) * Nout + cc] = l1;
            } else {
                if (cc < Nout) {
                    if (r0 < M)     *(float2*)&C[(size_t)r0 * Nout + cc] = v0;
                    if (r0 + 8 < M) *(float2*)&C[(size_t)(r0 + 8) * Nout + cc] = v1;
                }
            }
        }
    }
#endif
}

// ---------------------------- launch ---------------------------------------

static inline unsigned blocks_for(size_t total, int threads) {
    return (unsigned)((total + threads - 1) / threads);
}

extern "C" void kernel_launch(void* const* d_in, const int* in_sizes, int n_in,
                              void* d_out, int out_size) {
    const float* x  = (const float*)d_in[0];
    const int*   ei = (const int*)d_in[1];
    const int N = in_sizes[0] / 128;
    const int E = in_sizes[1] / 2;
    const int* src = ei;
    const int* dst = ei + E;
    const float* W1 = (const float*)d_in[2];  const float* b1 = (const float*)d_in[3];
    const float* W2 = (const float*)d_in[4];  const float* b2 = (const float*)d_in[5];
    const float* W3 = (const float*)d_in[6];  const float* b3 = (const float*)d_in[7];
    const float* W4 = (const float*)d_in[8];  const float* b4 = (const float*)d_in[9];
    const float* W5 = (const float*)d_in[10]; const float* b5 = (const float*)d_in[11];
    float* out = (float*)d_out;

    float *bufA, *bufB, *dinv, *csr_nrm;
    int *cnt, *rows, *pos, *partial, *csr_src;
    __nv_bfloat16 *wthi, *wtlo, *ahi, *alo, *bhi, *blo;
    cudaGetSymbolAddress((void**)&bufA, g_bufA);
    cudaGetSymbolAddress((void**)&bufB, g_bufB);
    cudaGetSymbolAddress((void**)&dinv, g_dinv);
    cudaGetSymbolAddress((void**)&cnt, g_cnt);
    cudaGetSymbolAddress((void**)&rows, g_rows);
    cudaGetSymbolAddress((void**)&pos, g_pos);
    cudaGetSymbolAddress((void**)&partial, g_partial);
    cudaGetSymbolAddress((void**)&csr_src, g_csr_src);
    cudaGetSymbolAddress((void**)&csr_nrm, g_csr_nrm);
    cudaGetSymbolAddress((void**)&wthi, g_wthi);
    cudaGetSymbolAddress((void**)&wtlo, g_wtlo);
    cudaGetSymbolAddress((void**)&ahi, g_ahi);
    cudaGetSymbolAddress((void**)&alo, g_alo);
    cudaGetSymbolAddress((void**)&bhi, g_bhi);
    cudaGetSymbolAddress((void**)&blo, g_blo);

    cudaFuncSetAttribute(k_mma_gemm<256, 2>,
                         cudaFuncAttributeMaxDynamicSharedMemorySize, MMA_SMEM);
    cudaFuncSetAttribute(k_mma_gemm<128, 3>,
                         cudaFuncAttributeMaxDynamicSharedMemorySize, MMA_SMEM);

    const int T = 256;
    const int nblk = (N + 255) / 256;
    const int mtiles = (N + 127) / 128;
    const int Mpad = mtiles * 128;

    // ---- CSR build (cnt pre-zeroed by previous call / static init) ----
    k_hist<<<blocks_for(E, T), T>>>(dst, cnt, E);
    k_scan_blk<<<nblk, T>>>(cnt, rows, partial, dinv, N);
    k_scan_add2<<<nblk, T>>>(rows, pos, partial, cnt, N, E);
    k_scatter<<<blocks_for(E, T), T>>>(src, dst, dinv, pos, csr_src, csr_nrm, E);

    // ---- weight transposes (one launch) ----
    k_wt_all<<<dim3(32, 32, 4), dim3(32, 8)>>>(W1, W2, W3, W4, wthi, wtlo);

    // ---- Layer 1: CSR-agg of x -> ahi/alo [*,128]; GEMM 128->1024
    //      (b1+relu) -> bhi/blo ----
    k_csr_agg_split<32, 0><<<(Mpad + 7) / 8, 256>>>(
        (const float4*)x, rows, csr_src, csr_nrm, dinv, nullptr,
        (uint2*)ahi, (uint2*)alo, N, Mpad);
    k_mma_gemm<256, 2><<<dim3(1024 / 256, mtiles), 256, MMA_SMEM>>>(
        ahi, alo, wthi + WOFF1, wtlo + WOFF1, b1, nullptr, bhi, blo,
        N, 128, 1024, 2);

    // ---- Layer 2: GEMM 1024->512 -> bufA; CSR-agg (+b2, relu) -> ahi/alo ----
    k_mma_gemm<256, 2><<<dim3(512 / 256, mtiles), 256, MMA_SMEM>>>(
        bhi, blo, wthi + WOFF2, wtlo + WOFF2, nullptr, bufA, nullptr, nullptr,
        N, 1024, 512, 0);
    k_csr_agg_split<128, 1><<<(Mpad + 1) / 2, 256>>>(
        (const float4*)bufA, rows, csr_src, csr_nrm, dinv, b2,
        (uint2*)ahi, (uint2*)alo, N, Mpad);

    // ---- Layer 3: GEMM 512->256 -> bufA; CSR-agg (+b3, relu) -> ahi/alo ----
    k_mma_gemm<256, 2><<<dim3(1, mtiles), 256, MMA_SMEM>>>(
        ahi, alo, wthi + WOFF3, wtlo + WOFF3, nullptr, bufA, nullptr, nullptr,
        N, 512, 256, 0);
    k_csr_agg_split<64, 1><<<(Mpad + 3) / 4, 256>>>(
        (const float4*)bufA, rows, csr_src, csr_nrm, dinv, b3,
        (uint2*)ahi, (uint2*)alo, N, Mpad);

    // ---- Layer 4: GEMM 256->64 (weights padded to 128 cols) -> bufA;
    //      fused CSR-agg (+b4) + relu + W5 matvec -> bufB (mv) ----
    k_mma_gemm<128, 3><<<dim3(1, mtiles), 256, MMA_SMEM>>>(
        ahi, alo, wthi + WOFF4, wtlo + WOFF4, nullptr, bufA, nullptr, nullptr,
        N, 256, 64, 0);
    k_csr_agg_mv<<<(N + 15) / 16, 256>>>(
        (const float4*)bufA, rows, csr_src, csr_nrm, dinv, b4, W5, bufB, N);

    // ---- Layer 5 tail: scalar CSR-agg into out ----
    k_out_scalar<<<nblk, T>>>(bufB, rows, csr_src, csr_nrm, dinv, b5, out, N);
}